// round 1
// baseline (speedup 1.0000x reference)
#include <cuda_runtime.h>

#define N_NODES 40000
#define N_EDGES 640000
#define DIM 128
#define RT 64            // rows per GEMM block
#define WS_STRIDE 132    // padded W-shared row stride (floats)
#define AS_STRIDE 68     // padded A-shared row stride (floats)

// Scratch (no cudaMalloc allowed)
__device__ float g_agg[N_NODES * DIM];
__device__ float g_h[N_NODES * DIM];
__device__ float g_colsum[DIM];
__device__ float g_colsumsq[DIM];
__device__ float g_scale[DIM];
__device__ float g_shift[DIM];

// ---------------------------------------------------------------------------
// K0: g_agg = (1 + gin_eps) * x ; zero the column-stat accumulators
// ---------------------------------------------------------------------------
__global__ void k0_init(const float* __restrict__ x,
                        const float* __restrict__ gin_eps) {
    const float c = 1.0f + __ldg(gin_eps);
    int idx = blockIdx.x * blockDim.x + threadIdx.x;
    const int total = N_NODES * DIM / 4;
    if (idx < total) {
        float4 v = ((const float4*)x)[idx];
        v.x *= c; v.y *= c; v.z *= c; v.w *= c;
        ((float4*)g_agg)[idx] = v;
    }
    if (blockIdx.x == 0 && threadIdx.x < DIM) {
        g_colsum[threadIdx.x]   = 0.0f;
        g_colsumsq[threadIdx.x] = 0.0f;
    }
}

// ---------------------------------------------------------------------------
// K1: edge scatter — one warp per edge, vectorized global reduction
//     agg[dst] += x[src]
// ---------------------------------------------------------------------------
__global__ void k1_scatter(const float* __restrict__ x,
                           const int* __restrict__ ei) {
    int warp = (blockIdx.x * blockDim.x + threadIdx.x) >> 5;
    int lane = threadIdx.x & 31;
    if (warp >= N_EDGES) return;
    int src = __ldg(&ei[warp]);            // row 0 of edge_index
    int dst = __ldg(&ei[N_EDGES + warp]);  // row 1 of edge_index

    float4 v = ((const float4*)x)[src * (DIM / 4) + lane];
    float* dp = g_agg + (size_t)dst * DIM + lane * 4;
    asm volatile("red.global.add.v4.f32 [%0], {%1, %2, %3, %4};"
                 :: "l"(dp), "f"(v.x), "f"(v.y), "f"(v.z), "f"(v.w)
                 : "memory");
}

// ---------------------------------------------------------------------------
// K2: h = agg @ W^T + b, fused per-column sum / sumsq accumulation for BN.
//     Block = 256 threads, 64 rows x 128 cols tile; thread = 4 rows x 8 cols.
//     W (transposed) and A-tile (transposed) staged in dynamic shared memory.
// ---------------------------------------------------------------------------
extern __shared__ float k2_smem[];

__global__ void __launch_bounds__(256, 2)
k2_gemm(const float* __restrict__ Wm, const float* __restrict__ bias) {
    float* Ws = k2_smem;                       // [DIM][WS_STRIDE] : Ws[k][n] = W[n][k]
    float* As = k2_smem + DIM * WS_STRIDE;     // [DIM][AS_STRIDE] : As[k][r] = A[row0+r][k]
    __shared__ float cs[DIM];
    __shared__ float cs2[DIM];

    const int tid = threadIdx.x;
    const int row0 = blockIdx.x * RT;

    // Load W transposed into shared
    for (int i = tid; i < DIM * DIM / 4; i += 256) {
        int n  = i >> 5;
        int k0 = (i & 31) << 2;
        float4 w = __ldg((const float4*)Wm + i);
        Ws[(k0 + 0) * WS_STRIDE + n] = w.x;
        Ws[(k0 + 1) * WS_STRIDE + n] = w.y;
        Ws[(k0 + 2) * WS_STRIDE + n] = w.z;
        Ws[(k0 + 3) * WS_STRIDE + n] = w.w;
    }
    // Load A tile transposed into shared
    for (int i = tid; i < RT * DIM / 4; i += 256) {
        int r  = i >> 5;
        int k0 = (i & 31) << 2;
        float4 a = *(const float4*)&g_agg[(size_t)(row0 + r) * DIM + k0];
        As[(k0 + 0) * AS_STRIDE + r] = a.x;
        As[(k0 + 1) * AS_STRIDE + r] = a.y;
        As[(k0 + 2) * AS_STRIDE + r] = a.z;
        As[(k0 + 3) * AS_STRIDE + r] = a.w;
    }
    if (tid < DIM) { cs[tid] = 0.0f; cs2[tid] = 0.0f; }
    __syncthreads();

    const int cg = tid & 15;   // col group: cols cg*8 .. cg*8+7
    const int rg = tid >> 4;   // row group: rows rg*4 .. rg*4+3

    float acc[4][8];
#pragma unroll
    for (int r = 0; r < 4; r++)
#pragma unroll
        for (int c = 0; c < 8; c++) acc[r][c] = 0.0f;

#pragma unroll 4
    for (int k = 0; k < DIM; k++) {
        float4 w0 = *(float4*)&Ws[k * WS_STRIDE + cg * 8];
        float4 w1 = *(float4*)&Ws[k * WS_STRIDE + cg * 8 + 4];
        float4 av = *(float4*)&As[k * AS_STRIDE + rg * 4];
        float a[4] = {av.x, av.y, av.z, av.w};
        float w[8] = {w0.x, w0.y, w0.z, w0.w, w1.x, w1.y, w1.z, w1.w};
#pragma unroll
        for (int r = 0; r < 4; r++)
#pragma unroll
            for (int c = 0; c < 8; c++) acc[r][c] = fmaf(a[r], w[c], acc[r][c]);
    }

    float bb[8];
#pragma unroll
    for (int c = 0; c < 8; c++) bb[c] = __ldg(&bias[cg * 8 + c]);

    float csum[8], csq[8];
#pragma unroll
    for (int c = 0; c < 8; c++) { csum[c] = 0.0f; csq[c] = 0.0f; }

#pragma unroll
    for (int r = 0; r < 4; r++) {
        int row = row0 + rg * 4 + r;
        float v[8];
#pragma unroll
        for (int c = 0; c < 8; c++) {
            v[c] = acc[r][c] + bb[c];
            csum[c] += v[c];
            csq[c]  += v[c] * v[c];
        }
        float4 o0 = {v[0], v[1], v[2], v[3]};
        float4 o1 = {v[4], v[5], v[6], v[7]};
        *(float4*)&g_h[(size_t)row * DIM + cg * 8]     = o0;
        *(float4*)&g_h[(size_t)row * DIM + cg * 8 + 4] = o1;
    }

#pragma unroll
    for (int c = 0; c < 8; c++) {
        atomicAdd(&cs[cg * 8 + c],  csum[c]);
        atomicAdd(&cs2[cg * 8 + c], csq[c]);
    }
    __syncthreads();
    if (tid < DIM) {
        atomicAdd(&g_colsum[tid],   cs[tid]);
        atomicAdd(&g_colsumsq[tid], cs2[tid]);
    }
}

// ---------------------------------------------------------------------------
// K2.5: per-column BN scale/shift from accumulated stats (128 threads)
// ---------------------------------------------------------------------------
__global__ void k25_stats(const float* __restrict__ gamma,
                          const float* __restrict__ beta) {
    int c = threadIdx.x;
    const float invN = 1.0f / (float)N_NODES;
    float mean = g_colsum[c] * invN;
    float var  = g_colsumsq[c] * invN - mean * mean;
    float inv  = rsqrtf(var + 1e-5f);
    float sc   = __ldg(&gamma[c]) * inv;
    g_scale[c] = sc;
    g_shift[c] = __ldg(&beta[c]) - mean * sc;
}

// ---------------------------------------------------------------------------
// K3: out = relu(h * scale + shift) + x
// ---------------------------------------------------------------------------
__global__ void k3_final(const float* __restrict__ x, float* __restrict__ out) {
    int idx = blockIdx.x * blockDim.x + threadIdx.x;
    const int total = N_NODES * DIM / 4;
    if (idx >= total) return;
    int c4 = idx & 31;  // float4-column index within the row
    float4 h  = ((const float4*)g_h)[idx];
    float4 xv = ((const float4*)x)[idx];
    float4 sc = ((const float4*)g_scale)[c4];
    float4 sh = ((const float4*)g_shift)[c4];
    float4 o;
    o.x = fmaxf(fmaf(h.x, sc.x, sh.x), 0.0f) + xv.x;
    o.y = fmaxf(fmaf(h.y, sc.y, sh.y), 0.0f) + xv.y;
    o.z = fmaxf(fmaf(h.z, sc.z, sh.z), 0.0f) + xv.z;
    o.w = fmaxf(fmaf(h.w, sc.w, sh.w), 0.0f) + xv.w;
    ((float4*)out)[idx] = o;
}

// ---------------------------------------------------------------------------
extern "C" void kernel_launch(void* const* d_in, const int* in_sizes, int n_in,
                              void* d_out, int out_size) {
    const float* x       = (const float*)d_in[0];
    const int*   ei      = (const int*)d_in[1];
    const float* Wm      = (const float*)d_in[2];
    const float* bias    = (const float*)d_in[3];
    const float* gamma   = (const float*)d_in[4];
    const float* beta    = (const float*)d_in[5];
    const float* gin_eps = (const float*)d_in[6];
    float* out = (float*)d_out;

    const int smem_k2 = (DIM * WS_STRIDE + DIM * AS_STRIDE) * sizeof(float);
    cudaFuncSetAttribute(k2_gemm, cudaFuncAttributeMaxDynamicSharedMemorySize, smem_k2);

    const int elem4 = N_NODES * DIM / 4;               // 1.28M
    k0_init<<<(elem4 + 255) / 256, 256>>>(x, gin_eps);
    k1_scatter<<<N_EDGES / 8, 256>>>(x, ei);           // 1 warp per edge
    k2_gemm<<<N_NODES / RT, 256, smem_k2>>>(Wm, bias);
    k25_stats<<<1, DIM>>>(gamma, beta);
    k3_final<<<(elem4 + 255) / 256, 256>>>(x, out);
}